// round 8
// baseline (speedup 1.0000x reference)
#include <cuda_runtime.h>
#include <cstdint>

// ----------------------------------------------------------------------------
// int8 GEMM (S,K)x(O,K)^T -> requantized (S,O), fused per-row scale.
//   acc[s,o] = sum_k x[s,k]*w[o,k]                      (int32, exact)
//   q[s,o]   = clip(rint(acc * sx*sw/sy[s]), -128, 127)
// HARNESS CONTRACT (deduced R3/R6/R7):
//   - inputs x, weight_q are int8 in the reference but the harness only
//     carries float32/int32/bf16 -> they arrive PROMOTED (int32 or float32).
//     A dtype-agnostic pre-pass converts them to packed int8 scratch.
//   - d_out is float32 [S*O out_q | S scale_y] (dual-output packing).
// GEMM: mma.sync m16n8k32 s8, cp.async double buffering, swizzled smem,
// ldmatrix fragment loads (verified consistent with explicit-LDS variant).
// ----------------------------------------------------------------------------

namespace {

constexpr int S_DIM = 8192;
constexpr int K_DIM = 1024;
constexpr int O_DIM = 4096;

constexpr int BM = 128;       // CTA tile M
constexpr int BN = 128;       // CTA tile N
constexpr int BK = 128;       // CTA tile K (bytes per smem row)
constexpr int NTHREADS = 256; // 8 warps: 2 (M) x 4 (N), warp tile 64x32
constexpr int NKTILES = K_DIM / BK; // 8

constexpr int A_TILE = BM * BK;     // 16 KB
constexpr int B_TILE = BN * BK;     // 16 KB
constexpr int SMEM_BYTES = 2 * (A_TILE + B_TILE); // 64 KB (double buffered)

// Swizzle: 128-byte rows, 16-byte quads, quad ^= (row & 7).
__device__ __forceinline__ uint32_t swz(uint32_t row, uint32_t q) {
    return row * (uint32_t)BK + ((q ^ (row & 7u)) << 4);
}

__device__ __forceinline__ void cp_async16(uint32_t saddr, const void* gptr) {
    asm volatile("cp.async.cg.shared.global [%0], [%1], 16;\n"
                 :: "r"(saddr), "l"(gptr));
}
__device__ __forceinline__ void cp_async_commit() {
    asm volatile("cp.async.commit_group;\n");
}
template <int N>
__device__ __forceinline__ void cp_async_wait() {
    asm volatile("cp.async.wait_group %0;\n" :: "n"(N));
}

__device__ __forceinline__ void ldmatrix_x4(uint32_t r[4], uint32_t saddr) {
    asm volatile("ldmatrix.sync.aligned.m8n8.x4.shared.b16 {%0,%1,%2,%3}, [%4];\n"
                 : "=r"(r[0]), "=r"(r[1]), "=r"(r[2]), "=r"(r[3])
                 : "r"(saddr));
}

__device__ __forceinline__ void mma_s8(int c[4], const uint32_t a[4],
                                       uint32_t b0, uint32_t b1) {
    asm volatile(
        "mma.sync.aligned.m16n8k32.row.col.s32.s8.s8.s32 "
        "{%0,%1,%2,%3}, {%4,%5,%6,%7}, {%8,%9}, {%0,%1,%2,%3};\n"
        : "+r"(c[0]), "+r"(c[1]), "+r"(c[2]), "+r"(c[3])
        : "r"(a[0]), "r"(a[1]), "r"(a[2]), "r"(a[3]), "r"(b0), "r"(b1));
}

__device__ __forceinline__ float quantize_f(int acc, float f) {
    float v = rintf((float)acc * f);          // fp32 mul + round-half-even == jnp
    return fminf(fmaxf(v, -128.0f), 127.0f);
}

// Dtype-agnostic 32-bit word -> int8 value.
// int32 in [-128,127]: top 24 bits all-0 or all-1. Otherwise treat the word
// as float32 (promoted int8 values are exactly representable). 0 safe in both.
__device__ __forceinline__ int8_t word_to_s8(uint32_t u) {
    uint32_t hi = u >> 8;
    int v;
    if (hi == 0u || hi == 0x00FFFFFFu) v = (int)u;
    else                               v = (int)__uint_as_float(u);
    v = max(-128, min(127, v));
    return (int8_t)v;
}

} // namespace

// 12 MB packed-int8 scratch (static device globals: allowed, no runtime alloc).
__device__ int8_t g_x8[(size_t)S_DIM * K_DIM];
__device__ int8_t g_w8[(size_t)O_DIM * K_DIM];

__global__ void convert_to_s8_kernel(const uint32_t* __restrict__ src,
                                     int8_t* __restrict__ dst, int n4) {
    int i = blockIdx.x * blockDim.x + threadIdx.x;
    if (i < n4) {
        uint4 u = reinterpret_cast<const uint4*>(src)[i];
        char4 c;
        c.x = word_to_s8(u.x);
        c.y = word_to_s8(u.y);
        c.z = word_to_s8(u.z);
        c.w = word_to_s8(u.w);
        reinterpret_cast<char4*>(dst)[i] = c;
    }
}

__global__ void __launch_bounds__(NTHREADS, 2)
int8_gemm_requant_kernel(const float* __restrict__ scale_x,
                         const float* __restrict__ scale_w,
                         const float* __restrict__ scale_y,
                         void* __restrict__ out_raw,
                         int out_float) {
    const int8_t* __restrict__ X = g_x8;
    const int8_t* __restrict__ W = g_w8;

    extern __shared__ int8_t smem[];
    int8_t* As = smem;                       // [2][BM*BK]
    int8_t* Bs = smem + 2 * A_TILE;          // [2][BN*BK]

    const uint32_t a_s32 = (uint32_t)__cvta_generic_to_shared(As);
    const uint32_t b_s32 = (uint32_t)__cvta_generic_to_shared(Bs);

    const int tid  = threadIdx.x;
    const int lane = tid & 31;
    const int wid  = tid >> 5;
    const int wm   = (wid & 1) * 64;   // warp M offset in CTA tile
    const int wn   = (wid >> 1) * 32;  // warp N offset in CTA tile

    const int bm = blockIdx.y * BM;
    const int bn = blockIdx.x * BN;

    const int8_t* Ag0 = X + (size_t)bm * K_DIM;
    const int8_t* Bg0 = W + (size_t)bn * K_DIM;

    auto load_tile = [&](int buf, int kt) {
        const int8_t* Ag = Ag0 + kt * BK;
        const int8_t* Bg = Bg0 + kt * BK;
        const uint32_t abase = a_s32 + (uint32_t)buf * A_TILE;
        const uint32_t bbase = b_s32 + (uint32_t)buf * B_TILE;
#pragma unroll
        for (int i = 0; i < 4; i++) {
            int idx = tid + i * NTHREADS;        // 0..1023
            int row = idx >> 3;                  // 0..127
            int q   = idx & 7;                   // 16B quad within 128B row
            cp_async16(abase + swz(row, q), Ag + (size_t)row * K_DIM + q * 16);
        }
#pragma unroll
        for (int i = 0; i < 4; i++) {
            int idx = tid + i * NTHREADS;
            int row = idx >> 3;
            int q   = idx & 7;
            cp_async16(bbase + swz(row, q), Bg + (size_t)row * K_DIM + q * 16);
        }
    };

    int acc[4][4][4];
#pragma unroll
    for (int mi = 0; mi < 4; mi++)
#pragma unroll
        for (int nj = 0; nj < 4; nj++)
#pragma unroll
            for (int r = 0; r < 4; r++) acc[mi][nj][r] = 0;

    load_tile(0, 0);
    cp_async_commit();

    const int rlo = lane & 15;   // ldmatrix row within 16-row group
    const int chi = lane >> 4;   // ldmatrix k-quad select (0/1 within k32)

    for (int kt = 0; kt < NKTILES; ++kt) {
        const int buf = kt & 1;
        if (kt + 1 < NKTILES) {
            load_tile(buf ^ 1, kt + 1);
            cp_async_commit();
            cp_async_wait<1>();
        } else {
            cp_async_wait<0>();
        }
        __syncthreads();

        const uint32_t abase = a_s32 + (uint32_t)buf * A_TILE;
        const uint32_t bbase = b_s32 + (uint32_t)buf * B_TILE;

#pragma unroll
        for (int s = 0; s < 4; s++) {          // 4 x k32 steps within BK=128
            uint32_t a[4][4], b[2][4];
#pragma unroll
            for (int mi = 0; mi < 4; mi++) {
                int row = wm + mi * 16 + rlo;
                ldmatrix_x4(a[mi], abase + swz(row, s * 2 + chi));
            }
#pragma unroll
            for (int nq = 0; nq < 2; nq++) {
                int row = wn + nq * 16 + rlo;
                ldmatrix_x4(b[nq], bbase + swz(row, s * 2 + chi));
            }
#pragma unroll
            for (int mi = 0; mi < 4; mi++) {
#pragma unroll
                for (int nj = 0; nj < 4; nj++) {
                    uint32_t b0 = b[nj >> 1][nj & 1];
                    uint32_t b1 = b[nj >> 1][2 + (nj & 1)];
                    mma_s8(acc[mi][nj], a[mi], b0, b1);
                }
            }
        }
        __syncthreads();
    }

    // --- epilogue: per-row requantization, exact fp32 match with reference
    const float sxw = scale_x[0] * scale_w[0];
    const int g  = lane >> 2;         // C-frag row within m8
    const int cl = (lane & 3) * 2;    // C-frag column pair

#pragma unroll
    for (int mi = 0; mi < 4; mi++) {
        int r0 = bm + wm + mi * 16 + g;
        int r1 = r0 + 8;
        float f0 = sxw / __ldg(scale_y + r0);
        float f1 = sxw / __ldg(scale_y + r1);
#pragma unroll
        for (int nj = 0; nj < 4; nj++) {
            int col = bn + wn + nj * 8 + cl;
            float q00 = quantize_f(acc[mi][nj][0], f0);
            float q01 = quantize_f(acc[mi][nj][1], f0);
            float q10 = quantize_f(acc[mi][nj][2], f1);
            float q11 = quantize_f(acc[mi][nj][3], f1);
            if (out_float) {
                float* out = (float*)out_raw;
                *reinterpret_cast<float2*>(out + (size_t)r0 * O_DIM + col) =
                    make_float2(q00, q01);
                *reinterpret_cast<float2*>(out + (size_t)r1 * O_DIM + col) =
                    make_float2(q10, q11);
            } else {
                int8_t* out = (int8_t*)out_raw;
                char2 v0, v1;
                v0.x = (int8_t)(int)q00; v0.y = (int8_t)(int)q01;
                v1.x = (int8_t)(int)q10; v1.y = (int8_t)(int)q11;
                *reinterpret_cast<char2*>(out + (size_t)r0 * O_DIM + col) = v0;
                *reinterpret_cast<char2*>(out + (size_t)r1 * O_DIM + col) = v1;
            }
        }
    }
}

__global__ void copy_scale_tail_kernel(const float* __restrict__ src,
                                       float* __restrict__ dst, int n) {
    int i = blockIdx.x * blockDim.x + threadIdx.x;
    if (i < n) dst[i] = src[i];
}

extern "C" void kernel_launch(void* const* d_in, const int* in_sizes, int n_in,
                              void* d_out, int out_size) {
    // --- identify inputs BY ELEMENT COUNT (robust to d_in ordering) ---
    const void*  x_raw = nullptr;   // S*K elements (promoted int8)
    const void*  w_raw = nullptr;   // O*K elements (promoted int8)
    const float* sx = nullptr;
    const float* sw = nullptr;
    const float* sy = nullptr;
    for (int i = 0; i < n_in; i++) {
        long long n = in_sizes[i];
        if      (n == (long long)S_DIM * K_DIM) x_raw = d_in[i];
        else if (n == (long long)O_DIM * K_DIM) w_raw = d_in[i];
        else if (n == S_DIM)                    sy = (const float*)d_in[i];
        else if (n == 1) { if (!sx) sx = (const float*)d_in[i];
                           else     sw = (const float*)d_in[i]; }
    }
    if (!x_raw) x_raw = d_in[0];
    if (!w_raw) w_raw = d_in[1];
    if (!sx) sx = (const float*)d_in[2];
    if (!sw) sw = (const float*)d_in[3];
    if (!sy) sy = (const float*)d_in[4];

    // --- pre-pass: promoted (int32-or-float32) -> packed int8 scratch ---
    int8_t* x8p = nullptr;
    int8_t* w8p = nullptr;
    cudaGetSymbolAddress((void**)&x8p, g_x8);
    cudaGetSymbolAddress((void**)&w8p, g_w8);
    {
        int n4x = (S_DIM * K_DIM) / 4;
        int n4w = (O_DIM * K_DIM) / 4;
        convert_to_s8_kernel<<<(n4x + 255) / 256, 256>>>(
            (const uint32_t*)x_raw, x8p, n4x);
        convert_to_s8_kernel<<<(n4w + 255) / 256, 256>>>(
            (const uint32_t*)w_raw, w8p, n4w);
    }

    const long long SO = (long long)S_DIM * O_DIM;
    const int out_float = ((long long)out_size >= SO + S_DIM) ? 1 : 0;

    cudaFuncSetAttribute(int8_gemm_requant_kernel,
                         cudaFuncAttributeMaxDynamicSharedMemorySize, SMEM_BYTES);

    dim3 grid(O_DIM / BN, S_DIM / BM);   // 32 x 64 = 2048 CTAs
    int8_gemm_requant_kernel<<<grid, NTHREADS, SMEM_BYTES>>>(
        sx, sw, sy, d_out, out_float);

    if (out_float) {
        copy_scale_tail_kernel<<<(S_DIM + 255) / 256, 256>>>(
            sy, (float*)d_out + SO, S_DIM);
    } else if ((long long)out_size > SO) {
        long long extra_bytes = (long long)out_size - SO;
        int nfloats = (int)(extra_bytes / 4);
        if (nfloats > S_DIM) nfloats = S_DIM;
        if (nfloats > 0) {
            copy_scale_tail_kernel<<<(nfloats + 255) / 256, 256>>>(
                sy, (float*)((char*)d_out + SO), nfloats);
        }
    }
}

// round 11
// speedup vs baseline: 1.1151x; 1.1151x over previous
#include <cuda_runtime.h>
#include <cstdint>

// ----------------------------------------------------------------------------
// int8 GEMM (S,K)x(O,K)^T -> requantized (S,O), fused per-row scale.
// R8 passed at 515us (legacy IMMA). tcgen05 is blocked: harness PTX targets
// plain sm_103 and ptxas rejects tcgen05.ld/wait -> cannot read TMEM.
// R9/R10 plan (resubmitted after container infra failure):
//   - CTA 128x64, warp tile 32x32 -> ~75 regs, 3 CTAs/SM (24 warps/SM)
//   - 3-stage cp.async pipeline, ONE __syncthreads per k-tile
//   - merged convert kernel + fused scale_y tail -> 2 launches (ncu hits GEMM)
// Contract (proven): inputs promoted (int32-or-f32) -> int8 scratch pre-pass;
// d_out = float32 [S*O out_q | S scale_y].
// ----------------------------------------------------------------------------

namespace {

constexpr int S_DIM = 8192;
constexpr int K_DIM = 1024;
constexpr int O_DIM = 4096;

constexpr int BM = 128;        // CTA tile M
constexpr int BN = 64;         // CTA tile N
constexpr int BK = 128;        // CTA tile K (bytes per smem row)
constexpr int NTHREADS = 256;  // 8 warps: 4 (M) x 2 (N), warp tile 32x32
constexpr int NKTILES = K_DIM / BK;  // 8
constexpr int STAGES = 3;

constexpr int A_TILE = BM * BK;      // 16 KB
constexpr int B_TILE = BN * BK;      // 8 KB
constexpr int SMEM_BYTES = STAGES * (A_TILE + B_TILE);  // 72 KB

// SW128 swizzle: 128-byte rows, 16-byte quads, quad ^= (row & 7).
__device__ __forceinline__ uint32_t swz(uint32_t row, uint32_t q) {
    return row * (uint32_t)BK + ((q ^ (row & 7u)) << 4);
}

__device__ __forceinline__ void cp_async16(uint32_t saddr, const void* gptr) {
    asm volatile("cp.async.cg.shared.global [%0], [%1], 16;\n" :: "r"(saddr), "l"(gptr));
}
__device__ __forceinline__ void cp_async_commit() {
    asm volatile("cp.async.commit_group;\n");
}
template <int N>
__device__ __forceinline__ void cp_async_wait() {
    asm volatile("cp.async.wait_group %0;\n" :: "n"(N));
}

__device__ __forceinline__ void ldmatrix_x4(uint32_t r[4], uint32_t saddr) {
    asm volatile("ldmatrix.sync.aligned.m8n8.x4.shared.b16 {%0,%1,%2,%3}, [%4];\n"
                 : "=r"(r[0]), "=r"(r[1]), "=r"(r[2]), "=r"(r[3])
                 : "r"(saddr));
}

__device__ __forceinline__ void mma_s8(int c[4], const uint32_t a[4],
                                       uint32_t b0, uint32_t b1) {
    asm volatile(
        "mma.sync.aligned.m16n8k32.row.col.s32.s8.s8.s32 "
        "{%0,%1,%2,%3}, {%4,%5,%6,%7}, {%8,%9}, {%0,%1,%2,%3};\n"
        : "+r"(c[0]), "+r"(c[1]), "+r"(c[2]), "+r"(c[3])
        : "r"(a[0]), "r"(a[1]), "r"(a[2]), "r"(a[3]), "r"(b0), "r"(b1));
}

__device__ __forceinline__ float quantize_f(int acc, float f) {
    float v = rintf((float)acc * f);          // fp32 mul + round-half-even == jnp
    return fminf(fmaxf(v, -128.0f), 127.0f);
}

// Dtype-agnostic promoted word -> int8 (proven in R8).
__device__ __forceinline__ int8_t word_to_s8(uint32_t u) {
    uint32_t hi = u >> 8;
    int v;
    if (hi == 0u || hi == 0x00FFFFFFu) v = (int)u;
    else                               v = (int)__uint_as_float(u);
    v = max(-128, min(127, v));
    return (int8_t)v;
}

} // namespace

__device__ int8_t g_x8[(size_t)S_DIM * K_DIM];
__device__ int8_t g_w8[(size_t)O_DIM * K_DIM];

// One kernel converts BOTH promoted inputs to packed int8 scratch.
__global__ void convert_both_kernel(const uint32_t* __restrict__ xsrc, int n4x,
                                    const uint32_t* __restrict__ wsrc, int n4w) {
    int i = blockIdx.x * blockDim.x + threadIdx.x;
    if (i < n4x) {
        uint4 u = reinterpret_cast<const uint4*>(xsrc)[i];
        char4 c;
        c.x = word_to_s8(u.x); c.y = word_to_s8(u.y);
        c.z = word_to_s8(u.z); c.w = word_to_s8(u.w);
        reinterpret_cast<char4*>(g_x8)[i] = c;
    } else if (i < n4x + n4w) {
        int j = i - n4x;
        uint4 u = reinterpret_cast<const uint4*>(wsrc)[j];
        char4 c;
        c.x = word_to_s8(u.x); c.y = word_to_s8(u.y);
        c.z = word_to_s8(u.z); c.w = word_to_s8(u.w);
        reinterpret_cast<char4*>(g_w8)[j] = c;
    }
}

__global__ void __launch_bounds__(NTHREADS, 3)
int8_gemm_requant_kernel(const float* __restrict__ scale_x,
                         const float* __restrict__ scale_w,
                         const float* __restrict__ scale_y,
                         void* __restrict__ out_raw,
                         int out_float) {
    extern __shared__ int8_t smem[];
    int8_t* As = smem;                          // [STAGES][A_TILE]
    int8_t* Bs = smem + STAGES * A_TILE;        // [STAGES][B_TILE]

    const uint32_t a_s32 = (uint32_t)__cvta_generic_to_shared(As);
    const uint32_t b_s32 = (uint32_t)__cvta_generic_to_shared(Bs);

    const int tid  = threadIdx.x;
    const int lane = tid & 31;
    const int wid  = tid >> 5;
    const int wm   = (wid & 3) * 32;   // warp M offset (4 warps over 128)
    const int wn   = (wid >> 2) * 32;  // warp N offset (2 warps over 64)

    const int bm = blockIdx.y * BM;
    const int bn = blockIdx.x * BN;

    const int8_t* Ag0 = g_x8 + (size_t)bm * K_DIM;
    const int8_t* Bg0 = g_w8 + (size_t)bn * K_DIM;

    // Loader: A 128 rows x 8 quads = 1024 quads (4/thread); B 512 quads (2/thread)
    auto load_tile = [&](int buf, int kt) {
        const int8_t* Ag = Ag0 + kt * BK;
        const int8_t* Bg = Bg0 + kt * BK;
        const uint32_t abase = a_s32 + (uint32_t)buf * A_TILE;
        const uint32_t bbase = b_s32 + (uint32_t)buf * B_TILE;
#pragma unroll
        for (int i = 0; i < 4; i++) {
            int idx = tid + i * NTHREADS;        // 0..1023
            int row = idx >> 3;                  // 0..127
            int q   = idx & 7;
            cp_async16(abase + swz(row, q), Ag + (size_t)row * K_DIM + q * 16);
        }
#pragma unroll
        for (int i = 0; i < 2; i++) {
            int idx = tid + i * NTHREADS;        // 0..511
            int row = idx >> 3;                  // 0..63
            int q   = idx & 7;
            cp_async16(bbase + swz(row, q), Bg + (size_t)row * K_DIM + q * 16);
        }
        cp_async_commit();
    };

    int acc[2][4][4];
#pragma unroll
    for (int mi = 0; mi < 2; mi++)
#pragma unroll
        for (int nj = 0; nj < 4; nj++)
#pragma unroll
            for (int r = 0; r < 4; r++) acc[mi][nj][r] = 0;

    // Prologue: fill STAGES-1 buffers.
    load_tile(0, 0);
    load_tile(1, 1);

    const int rlo = lane & 15;   // ldmatrix row within 16-row group
    const int chi = lane >> 4;   // k16-half select within k32

    for (int kt = 0; kt < NKTILES; ++kt) {
        if (kt + STAGES - 1 < NKTILES) cp_async_wait<STAGES - 2>();
        else                           cp_async_wait<0>();
        __syncthreads();             // tile kt resident; prior-buffer readers done

        if (kt + STAGES - 1 < NKTILES)
            load_tile((kt + STAGES - 1) % STAGES, kt + STAGES - 1);

        const int buf = kt % STAGES;
        const uint32_t abase = a_s32 + (uint32_t)buf * A_TILE;
        const uint32_t bbase = b_s32 + (uint32_t)buf * B_TILE;

#pragma unroll
        for (int s = 0; s < 4; s++) {          // 4 x k32 steps within BK=128
            uint32_t a[2][4], b[2][4];
#pragma unroll
            for (int mi = 0; mi < 2; mi++) {
                int row = wm + mi * 16 + rlo;
                ldmatrix_x4(a[mi], abase + swz(row, s * 2 + chi));
            }
#pragma unroll
            for (int nq = 0; nq < 2; nq++) {
                int row = wn + nq * 16 + rlo;
                ldmatrix_x4(b[nq], bbase + swz(row, s * 2 + chi));
            }
#pragma unroll
            for (int mi = 0; mi < 2; mi++) {
#pragma unroll
                for (int nj = 0; nj < 4; nj++) {
                    uint32_t b0 = b[nj >> 1][nj & 1];
                    uint32_t b1 = b[nj >> 1][2 + (nj & 1)];
                    mma_s8(acc[mi][nj], a[mi], b0, b1);
                }
            }
        }
    }

    // --- epilogue: per-row requantization, exact fp32 match with reference
    const float sxw = scale_x[0] * scale_w[0];
    const int g  = lane >> 2;         // C-frag row within m8
    const int cl = (lane & 3) * 2;    // C-frag column pair

#pragma unroll
    for (int mi = 0; mi < 2; mi++) {
        int r0 = bm + wm + mi * 16 + g;
        int r1 = r0 + 8;
        float f0 = sxw / __ldg(scale_y + r0);
        float f1 = sxw / __ldg(scale_y + r1);
#pragma unroll
        for (int nj = 0; nj < 4; nj++) {
            int col = bn + wn + nj * 8 + cl;
            float q00 = quantize_f(acc[mi][nj][0], f0);
            float q01 = quantize_f(acc[mi][nj][1], f0);
            float q10 = quantize_f(acc[mi][nj][2], f1);
            float q11 = quantize_f(acc[mi][nj][3], f1);
            if (out_float) {
                float* out = (float*)out_raw;
                *reinterpret_cast<float2*>(out + (size_t)r0 * O_DIM + col) =
                    make_float2(q00, q01);
                *reinterpret_cast<float2*>(out + (size_t)r1 * O_DIM + col) =
                    make_float2(q10, q11);
            } else {
                int8_t* out = (int8_t*)out_raw;
                char2 v0, v1;
                v0.x = (int8_t)(int)q00; v0.y = (int8_t)(int)q01;
                v1.x = (int8_t)(int)q10; v1.y = (int8_t)(int)q11;
                *reinterpret_cast<char2*>(out + (size_t)r0 * O_DIM + col) = v0;
                *reinterpret_cast<char2*>(out + (size_t)r1 * O_DIM + col) = v1;
            }
        }
    }

    // Fused scale_y tail (one CTA), float mode only.
    if (out_float && blockIdx.x == 0 && blockIdx.y == 0) {
        float* tail = (float*)out_raw + (size_t)S_DIM * O_DIM;
        for (int i = tid; i < S_DIM; i += NTHREADS) tail[i] = scale_y[i];
    }
}

extern "C" void kernel_launch(void* const* d_in, const int* in_sizes, int n_in,
                              void* d_out, int out_size) {
    // Identify inputs BY ELEMENT COUNT (robust to d_in ordering).
    const void*  x_raw = nullptr;
    const void*  w_raw = nullptr;
    const float* sx = nullptr;
    const float* sw = nullptr;
    const float* sy = nullptr;
    for (int i = 0; i < n_in; i++) {
        long long n = in_sizes[i];
        if      (n == (long long)S_DIM * K_DIM) x_raw = d_in[i];
        else if (n == (long long)O_DIM * K_DIM) w_raw = d_in[i];
        else if (n == S_DIM)                    sy = (const float*)d_in[i];
        else if (n == 1) { if (!sx) sx = (const float*)d_in[i];
                           else     sw = (const float*)d_in[i]; }
    }
    if (!x_raw) x_raw = d_in[0];
    if (!w_raw) w_raw = d_in[1];
    if (!sx) sx = (const float*)d_in[2];
    if (!sw) sw = (const float*)d_in[3];
    if (!sy) sy = (const float*)d_in[4];

    const int n4x = (S_DIM * K_DIM) / 4;
    const int n4w = (O_DIM * K_DIM) / 4;
    convert_both_kernel<<<(n4x + n4w + 255) / 256, 256>>>(
        (const uint32_t*)x_raw, n4x, (const uint32_t*)w_raw, n4w);

    const long long SO = (long long)S_DIM * O_DIM;
    const int out_float = ((long long)out_size >= SO + S_DIM) ? 1 : 0;

    cudaFuncSetAttribute(int8_gemm_requant_kernel,
                         cudaFuncAttributeMaxDynamicSharedMemorySize, SMEM_BYTES);

    dim3 grid(O_DIM / BN, S_DIM / BM);   // 64 x 64 = 4096 CTAs
    int8_gemm_requant_kernel<<<grid, NTHREADS, SMEM_BYTES>>>(
        sx, sw, sy, d_out, out_float);
}

// round 13
// speedup vs baseline: 2.4336x; 2.1825x over previous
#include <cuda_runtime.h>
#include <cuda_bf16.h>
#include <cstdint>

// ----------------------------------------------------------------------------
// int8 GEMM (S,K)x(O,K)^T -> requantized (S,O), fused per-row scale.
// R11: legacy s8 IMMA saturated tensor pipe at ~60cyc/mma -> 462us. The s8
// mma.sync path is emulation-grade on sm_103 (native int8 = tcgen05 only,
// which this toolchain rejects). R12/R13: bf16 HMMA mainloop (m16n8k16,
// fp32 accum). EXACT: int8 values exact in bf16, products exact in fp32,
// |sum| <= 1024*127*127 < 2^24 -> fp32 accumulation exact.
// (Resubmission: R12 bench died at harness init, "device busy" = infra.)
// Contract (proven): inputs promoted (int32-or-f32) -> scratch pre-pass;
// d_out = float32 [S*O out_q | S scale_y].
// ----------------------------------------------------------------------------

namespace {

constexpr int S_DIM = 8192;
constexpr int K_DIM = 1024;
constexpr int O_DIM = 4096;

constexpr int BM = 128;        // CTA tile M
constexpr int BN = 128;        // CTA tile N
constexpr int BKE = 64;        // K elements per tile (= 128 bytes per smem row)
constexpr int BKB = 128;       // K bytes per smem row (SW128 atom)
constexpr int NTHREADS = 256;  // 8 warps: 2 (M) x 4 (N), warp tile 64x32
constexpr int NKTILES = K_DIM / BKE;  // 16
constexpr int STAGES = 3;

constexpr int A_TILE = BM * BKB;     // 16 KB
constexpr int B_TILE = BN * BKB;     // 16 KB
constexpr int SMEM_BYTES = STAGES * (A_TILE + B_TILE);  // 96 KB

// SW128 swizzle: 128-byte rows, 16-byte quads, quad ^= (row & 7).
__device__ __forceinline__ uint32_t swz(uint32_t row, uint32_t q) {
    return row * (uint32_t)BKB + ((q ^ (row & 7u)) << 4);
}

__device__ __forceinline__ void cp_async16(uint32_t saddr, const void* gptr) {
    asm volatile("cp.async.cg.shared.global [%0], [%1], 16;\n" :: "r"(saddr), "l"(gptr));
}
__device__ __forceinline__ void cp_async_commit() {
    asm volatile("cp.async.commit_group;\n");
}
template <int N>
__device__ __forceinline__ void cp_async_wait() {
    asm volatile("cp.async.wait_group %0;\n" :: "n"(N));
}

__device__ __forceinline__ void ldmatrix_x4(uint32_t r[4], uint32_t saddr) {
    asm volatile("ldmatrix.sync.aligned.m8n8.x4.shared.b16 {%0,%1,%2,%3}, [%4];\n"
                 : "=r"(r[0]), "=r"(r[1]), "=r"(r[2]), "=r"(r[3])
                 : "r"(saddr));
}

// bf16 MMA, fp32 accumulate: D(16x8) += A(16x16) * B(16x8)
__device__ __forceinline__ void mma_bf16(float c[4], const uint32_t a[4],
                                         uint32_t b0, uint32_t b1) {
    asm volatile(
        "mma.sync.aligned.m16n8k16.row.col.f32.bf16.bf16.f32 "
        "{%0,%1,%2,%3}, {%4,%5,%6,%7}, {%8,%9}, {%0,%1,%2,%3};\n"
        : "+f"(c[0]), "+f"(c[1]), "+f"(c[2]), "+f"(c[3])
        : "r"(a[0]), "r"(a[1]), "r"(a[2]), "r"(a[3]), "r"(b0), "r"(b1));
}

__device__ __forceinline__ float quantize_f(float acc, float f) {
    float v = rintf(acc * f);                 // fp32 mul + round-half-even == jnp
    return fminf(fmaxf(v, -128.0f), 127.0f);
}

// Dtype-agnostic promoted word -> small int value (proven in R8).
__device__ __forceinline__ int word_to_int(uint32_t u) {
    uint32_t hi = u >> 8;
    int v;
    if (hi == 0u || hi == 0x00FFFFFFu) v = (int)u;
    else                               v = (int)__uint_as_float(u);
    return max(-128, min(127, v));
}

} // namespace

// bf16 scratch: 16 MB + 8 MB (static device globals: allowed).
__device__ __nv_bfloat16 g_xh[(size_t)S_DIM * K_DIM];
__device__ __nv_bfloat16 g_wh[(size_t)O_DIM * K_DIM];

// Convert BOTH promoted inputs to bf16 scratch (exact for int8 range).
__global__ void convert_both_kernel(const uint32_t* __restrict__ xsrc, int n4x,
                                    const uint32_t* __restrict__ wsrc, int n4w) {
    int i = blockIdx.x * blockDim.x + threadIdx.x;
    if (i < n4x) {
        uint4 u = reinterpret_cast<const uint4*>(xsrc)[i];
        __nv_bfloat162 p0 = __floats2bfloat162_rn((float)word_to_int(u.x),
                                                  (float)word_to_int(u.y));
        __nv_bfloat162 p1 = __floats2bfloat162_rn((float)word_to_int(u.z),
                                                  (float)word_to_int(u.w));
        reinterpret_cast<__nv_bfloat162*>(g_xh)[i * 2 + 0] = p0;
        reinterpret_cast<__nv_bfloat162*>(g_xh)[i * 2 + 1] = p1;
    } else if (i < n4x + n4w) {
        int j = i - n4x;
        uint4 u = reinterpret_cast<const uint4*>(wsrc)[j];
        __nv_bfloat162 p0 = __floats2bfloat162_rn((float)word_to_int(u.x),
                                                  (float)word_to_int(u.y));
        __nv_bfloat162 p1 = __floats2bfloat162_rn((float)word_to_int(u.z),
                                                  (float)word_to_int(u.w));
        reinterpret_cast<__nv_bfloat162*>(g_wh)[j * 2 + 0] = p0;
        reinterpret_cast<__nv_bfloat162*>(g_wh)[j * 2 + 1] = p1;
    }
}

__global__ void __launch_bounds__(NTHREADS, 2)
bf16_gemm_requant_kernel(const float* __restrict__ scale_x,
                         const float* __restrict__ scale_w,
                         const float* __restrict__ scale_y,
                         void* __restrict__ out_raw,
                         int out_float) {
    extern __shared__ int8_t smem[];
    int8_t* As = smem;                          // [STAGES][A_TILE]
    int8_t* Bs = smem + STAGES * A_TILE;        // [STAGES][B_TILE]

    const uint32_t a_s32 = (uint32_t)__cvta_generic_to_shared(As);
    const uint32_t b_s32 = (uint32_t)__cvta_generic_to_shared(Bs);

    const int tid  = threadIdx.x;
    const int lane = tid & 31;
    const int wid  = tid >> 5;
    const int wm   = (wid & 1) * 64;   // warp M offset (2 warps over 128)
    const int wn   = (wid >> 1) * 32;  // warp N offset (4 warps over 128)

    const int bm = blockIdx.y * BM;
    const int bn = blockIdx.x * BN;

    const __nv_bfloat16* Ag0 = g_xh + (size_t)bm * K_DIM;
    const __nv_bfloat16* Bg0 = g_wh + (size_t)bn * K_DIM;

    // Loader: 128 rows x 8 quads (16B) per operand = 1024 quads -> 4/thread.
    auto load_tile = [&](int buf, int kt) {
        const __nv_bfloat16* Ag = Ag0 + kt * BKE;
        const __nv_bfloat16* Bg = Bg0 + kt * BKE;
        const uint32_t abase = a_s32 + (uint32_t)buf * A_TILE;
        const uint32_t bbase = b_s32 + (uint32_t)buf * B_TILE;
#pragma unroll
        for (int i = 0; i < 4; i++) {
            int idx = tid + i * NTHREADS;        // 0..1023
            int row = idx >> 3;                  // 0..127
            int q   = idx & 7;                   // 16B quad = 8 bf16
            cp_async16(abase + swz(row, q), Ag + (size_t)row * K_DIM + q * 8);
        }
#pragma unroll
        for (int i = 0; i < 4; i++) {
            int idx = tid + i * NTHREADS;
            int row = idx >> 3;
            int q   = idx & 7;
            cp_async16(bbase + swz(row, q), Bg + (size_t)row * K_DIM + q * 8);
        }
        cp_async_commit();
    };

    float acc[4][4][4];
#pragma unroll
    for (int mi = 0; mi < 4; mi++)
#pragma unroll
        for (int nj = 0; nj < 4; nj++)
#pragma unroll
            for (int r = 0; r < 4; r++) acc[mi][nj][r] = 0.0f;

    // Prologue: fill STAGES-1 buffers.
    load_tile(0, 0);
    load_tile(1, 1);

    const int rlo = lane & 15;   // ldmatrix row within 16-row group
    const int chi = lane >> 4;   // k8-half select within k16 (16B quad)

    for (int kt = 0; kt < NKTILES; ++kt) {
        if (kt + STAGES - 1 < NKTILES) cp_async_wait<STAGES - 2>();
        else                           cp_async_wait<0>();
        __syncthreads();             // tile kt resident; prior-buffer readers done

        if (kt + STAGES - 1 < NKTILES)
            load_tile((kt + STAGES - 1) % STAGES, kt + STAGES - 1);

        const int buf = kt % STAGES;
        const uint32_t abase = a_s32 + (uint32_t)buf * A_TILE;
        const uint32_t bbase = b_s32 + (uint32_t)buf * B_TILE;

#pragma unroll
        for (int s = 0; s < 4; s++) {          // 4 x k16 steps within BKE=64
            uint32_t a[4][4], b[2][4];
#pragma unroll
            for (int mi = 0; mi < 4; mi++) {
                int row = wm + mi * 16 + rlo;
                ldmatrix_x4(a[mi], abase + swz(row, s * 2 + chi));
            }
#pragma unroll
            for (int nq = 0; nq < 2; nq++) {
                int row = wn + nq * 16 + rlo;
                ldmatrix_x4(b[nq], bbase + swz(row, s * 2 + chi));
            }
#pragma unroll
            for (int mi = 0; mi < 4; mi++) {
#pragma unroll
                for (int nj = 0; nj < 4; nj++) {
                    uint32_t b0 = b[nj >> 1][nj & 1];      // k 0-7,  n8-tile nj
                    uint32_t b1 = b[nj >> 1][2 + (nj & 1)];// k 8-15, n8-tile nj
                    mma_bf16(acc[mi][nj], a[mi], b0, b1);
                }
            }
        }
    }

    // --- epilogue: acc is the EXACT integer sum as fp32; requant == reference
    const float sxw = scale_x[0] * scale_w[0];
    const int g  = lane >> 2;         // C-frag row within m8
    const int cl = (lane & 3) * 2;    // C-frag column pair

#pragma unroll
    for (int mi = 0; mi < 4; mi++) {
        int r0 = bm + wm + mi * 16 + g;
        int r1 = r0 + 8;
        float f0 = sxw / __ldg(scale_y + r0);
        float f1 = sxw / __ldg(scale_y + r1);
#pragma unroll
        for (int nj = 0; nj < 4; nj++) {
            int col = bn + wn + nj * 8 + cl;
            float q00 = quantize_f(acc[mi][nj][0], f0);
            float q01 = quantize_f(acc[mi][nj][1], f0);
            float q10 = quantize_f(acc[mi][nj][2], f1);
            float q11 = quantize_f(acc[mi][nj][3], f1);
            if (out_float) {
                float* out = (float*)out_raw;
                *reinterpret_cast<float2*>(out + (size_t)r0 * O_DIM + col) =
                    make_float2(q00, q01);
                *reinterpret_cast<float2*>(out + (size_t)r1 * O_DIM + col) =
                    make_float2(q10, q11);
            } else {
                int8_t* out = (int8_t*)out_raw;
                char2 v0, v1;
                v0.x = (int8_t)(int)q00; v0.y = (int8_t)(int)q01;
                v1.x = (int8_t)(int)q10; v1.y = (int8_t)(int)q11;
                *reinterpret_cast<char2*>(out + (size_t)r0 * O_DIM + col) = v0;
                *reinterpret_cast<char2*>(out + (size_t)r1 * O_DIM + col) = v1;
            }
        }
    }

    // Fused scale_y tail (one CTA), float mode only.
    if (out_float && blockIdx.x == 0 && blockIdx.y == 0) {
        float* tail = (float*)out_raw + (size_t)S_DIM * O_DIM;
        for (int i = tid; i < S_DIM; i += NTHREADS) tail[i] = scale_y[i];
    }
}

extern "C" void kernel_launch(void* const* d_in, const int* in_sizes, int n_in,
                              void* d_out, int out_size) {
    // Identify inputs BY ELEMENT COUNT (robust to d_in ordering).
    const void*  x_raw = nullptr;
    const void*  w_raw = nullptr;
    const float* sx = nullptr;
    const float* sw = nullptr;
    const float* sy = nullptr;
    for (int i = 0; i < n_in; i++) {
        long long n = in_sizes[i];
        if      (n == (long long)S_DIM * K_DIM) x_raw = d_in[i];
        else if (n == (long long)O_DIM * K_DIM) w_raw = d_in[i];
        else if (n == S_DIM)                    sy = (const float*)d_in[i];
        else if (n == 1) { if (!sx) sx = (const float*)d_in[i];
                           else     sw = (const float*)d_in[i]; }
    }
    if (!x_raw) x_raw = d_in[0];
    if (!w_raw) w_raw = d_in[1];
    if (!sx) sx = (const float*)d_in[2];
    if (!sw) sw = (const float*)d_in[3];
    if (!sy) sy = (const float*)d_in[4];

    const int n4x = (S_DIM * K_DIM) / 4;
    const int n4w = (O_DIM * K_DIM) / 4;
    convert_both_kernel<<<(n4x + n4w + 255) / 256, 256>>>(
        (const uint32_t*)x_raw, n4x, (const uint32_t*)w_raw, n4w);

    const long long SO = (long long)S_DIM * O_DIM;
    const int out_float = ((long long)out_size >= SO + S_DIM) ? 1 : 0;

    cudaFuncSetAttribute(bf16_gemm_requant_kernel,
                         cudaFuncAttributeMaxDynamicSharedMemorySize, SMEM_BYTES);

    dim3 grid(O_DIM / BN, S_DIM / BM);   // 32 x 64 = 2048 CTAs
    bf16_gemm_requant_kernel<<<grid, NTHREADS, SMEM_BYTES>>>(
        sx, sw, sy, d_out, out_float);
}

// round 15
// speedup vs baseline: 2.4889x; 1.0227x over previous
#include <cuda_runtime.h>
#include <cuda_bf16.h>
#include <cstdint>

// ----------------------------------------------------------------------------
// int8 GEMM (S,K)x(O,K)^T -> requantized (S,O), fused per-row scale.
// R13: bf16 HMMA mainloop passed at 211.7us (GEMM 195.8), tensor=57.7%,
// occ=24% (acc-reg capped), issue=37% -> pipe idles because __syncthreads
// phase-locks all warps into collective LDSM-then-MMA phases.
// R14/R15: per-warp rotation of the k16 step order (legal: fp32 accumulation
// is EXACT here, order-independent) + next-tile cp.async issued after the
// first step to overlap the LSU burst with tensor work.
// (Resubmission: R14 bench died in broker infra before running.)
// Contract (proven): inputs promoted (int32-or-f32) -> bf16 scratch pre-pass;
// d_out = float32 [S*O out_q | S scale_y].
// ----------------------------------------------------------------------------

namespace {

constexpr int S_DIM = 8192;
constexpr int K_DIM = 1024;
constexpr int O_DIM = 4096;

constexpr int BM = 128;        // CTA tile M
constexpr int BN = 128;        // CTA tile N
constexpr int BKE = 64;        // K elements per tile (= 128 bytes per smem row)
constexpr int BKB = 128;       // K bytes per smem row (SW128 atom)
constexpr int NTHREADS = 256;  // 8 warps: 2 (M) x 4 (N), warp tile 64x32
constexpr int NKTILES = K_DIM / BKE;  // 16
constexpr int STAGES = 3;

constexpr int A_TILE = BM * BKB;     // 16 KB
constexpr int B_TILE = BN * BKB;     // 16 KB
constexpr int SMEM_BYTES = STAGES * (A_TILE + B_TILE);  // 96 KB

// SW128 swizzle: 128-byte rows, 16-byte quads, quad ^= (row & 7).
__device__ __forceinline__ uint32_t swz(uint32_t row, uint32_t q) {
    return row * (uint32_t)BKB + ((q ^ (row & 7u)) << 4);
}

__device__ __forceinline__ void cp_async16(uint32_t saddr, const void* gptr) {
    asm volatile("cp.async.cg.shared.global [%0], [%1], 16;\n" :: "r"(saddr), "l"(gptr));
}
__device__ __forceinline__ void cp_async_commit() {
    asm volatile("cp.async.commit_group;\n");
}
template <int N>
__device__ __forceinline__ void cp_async_wait() {
    asm volatile("cp.async.wait_group %0;\n" :: "n"(N));
}

__device__ __forceinline__ void ldmatrix_x4(uint32_t r[4], uint32_t saddr) {
    asm volatile("ldmatrix.sync.aligned.m8n8.x4.shared.b16 {%0,%1,%2,%3}, [%4];\n"
                 : "=r"(r[0]), "=r"(r[1]), "=r"(r[2]), "=r"(r[3])
                 : "r"(saddr));
}

// bf16 MMA, fp32 accumulate: D(16x8) += A(16x16) * B(16x8)
__device__ __forceinline__ void mma_bf16(float c[4], const uint32_t a[4],
                                         uint32_t b0, uint32_t b1) {
    asm volatile(
        "mma.sync.aligned.m16n8k16.row.col.f32.bf16.bf16.f32 "
        "{%0,%1,%2,%3}, {%4,%5,%6,%7}, {%8,%9}, {%0,%1,%2,%3};\n"
        : "+f"(c[0]), "+f"(c[1]), "+f"(c[2]), "+f"(c[3])
        : "r"(a[0]), "r"(a[1]), "r"(a[2]), "r"(a[3]), "r"(b0), "r"(b1));
}

__device__ __forceinline__ float quantize_f(float acc, float f) {
    float v = rintf(acc * f);                 // fp32 mul + round-half-even == jnp
    return fminf(fmaxf(v, -128.0f), 127.0f);
}

// Dtype-agnostic promoted word -> small int value (proven in R8).
__device__ __forceinline__ int word_to_int(uint32_t u) {
    uint32_t hi = u >> 8;
    int v;
    if (hi == 0u || hi == 0x00FFFFFFu) v = (int)u;
    else                               v = (int)__uint_as_float(u);
    return max(-128, min(127, v));
}

} // namespace

// bf16 scratch: 16 MB + 8 MB (static device globals: allowed).
__device__ __nv_bfloat16 g_xh[(size_t)S_DIM * K_DIM];
__device__ __nv_bfloat16 g_wh[(size_t)O_DIM * K_DIM];

// Convert BOTH promoted inputs to bf16 scratch (exact for int8 range).
__global__ void convert_both_kernel(const uint32_t* __restrict__ xsrc, int n4x,
                                    const uint32_t* __restrict__ wsrc, int n4w) {
    int i = blockIdx.x * blockDim.x + threadIdx.x;
    if (i < n4x) {
        uint4 u = reinterpret_cast<const uint4*>(xsrc)[i];
        __nv_bfloat162 p0 = __floats2bfloat162_rn((float)word_to_int(u.x),
                                                  (float)word_to_int(u.y));
        __nv_bfloat162 p1 = __floats2bfloat162_rn((float)word_to_int(u.z),
                                                  (float)word_to_int(u.w));
        reinterpret_cast<__nv_bfloat162*>(g_xh)[i * 2 + 0] = p0;
        reinterpret_cast<__nv_bfloat162*>(g_xh)[i * 2 + 1] = p1;
    } else if (i < n4x + n4w) {
        int j = i - n4x;
        uint4 u = reinterpret_cast<const uint4*>(wsrc)[j];
        __nv_bfloat162 p0 = __floats2bfloat162_rn((float)word_to_int(u.x),
                                                  (float)word_to_int(u.y));
        __nv_bfloat162 p1 = __floats2bfloat162_rn((float)word_to_int(u.z),
                                                  (float)word_to_int(u.w));
        reinterpret_cast<__nv_bfloat162*>(g_wh)[j * 2 + 0] = p0;
        reinterpret_cast<__nv_bfloat162*>(g_wh)[j * 2 + 1] = p1;
    }
}

__global__ void __launch_bounds__(NTHREADS, 2)
bf16_gemm_requant_kernel(const float* __restrict__ scale_x,
                         const float* __restrict__ scale_w,
                         const float* __restrict__ scale_y,
                         void* __restrict__ out_raw,
                         int out_float) {
    extern __shared__ int8_t smem[];
    int8_t* As = smem;                          // [STAGES][A_TILE]
    int8_t* Bs = smem + STAGES * A_TILE;        // [STAGES][B_TILE]

    const uint32_t a_s32 = (uint32_t)__cvta_generic_to_shared(As);
    const uint32_t b_s32 = (uint32_t)__cvta_generic_to_shared(Bs);

    const int tid  = threadIdx.x;
    const int lane = tid & 31;
    const int wid  = tid >> 5;
    const int wm   = (wid & 1) * 64;   // warp M offset (2 warps over 128)
    const int wn   = (wid >> 1) * 32;  // warp N offset (4 warps over 128)

    const int bm = blockIdx.y * BM;
    const int bn = blockIdx.x * BN;

    const __nv_bfloat16* Ag0 = g_xh + (size_t)bm * K_DIM;
    const __nv_bfloat16* Bg0 = g_wh + (size_t)bn * K_DIM;

    // Loader: 128 rows x 8 quads (16B) per operand = 1024 quads -> 4/thread.
    auto load_tile = [&](int buf, int kt) {
        const __nv_bfloat16* Ag = Ag0 + kt * BKE;
        const __nv_bfloat16* Bg = Bg0 + kt * BKE;
        const uint32_t abase = a_s32 + (uint32_t)buf * A_TILE;
        const uint32_t bbase = b_s32 + (uint32_t)buf * B_TILE;
#pragma unroll
        for (int i = 0; i < 4; i++) {
            int idx = tid + i * NTHREADS;        // 0..1023
            int row = idx >> 3;                  // 0..127
            int q   = idx & 7;                   // 16B quad = 8 bf16
            cp_async16(abase + swz(row, q), Ag + (size_t)row * K_DIM + q * 8);
        }
#pragma unroll
        for (int i = 0; i < 4; i++) {
            int idx = tid + i * NTHREADS;
            int row = idx >> 3;
            int q   = idx & 7;
            cp_async16(bbase + swz(row, q), Bg + (size_t)row * K_DIM + q * 8);
        }
        cp_async_commit();
    };

    float acc[4][4][4];
#pragma unroll
    for (int mi = 0; mi < 4; mi++)
#pragma unroll
        for (int nj = 0; nj < 4; nj++)
#pragma unroll
            for (int r = 0; r < 4; r++) acc[mi][nj][r] = 0.0f;

    // Prologue: fill STAGES-1 buffers.
    load_tile(0, 0);
    load_tile(1, 1);

    const int rlo = lane & 15;   // ldmatrix row within 16-row group
    const int chi = lane >> 4;   // k8-half select within k16 (16B quad)
    const int srot = wid & 3;    // per-warp k16-step rotation (de-phases warps)

    for (int kt = 0; kt < NKTILES; ++kt) {
        if (kt + STAGES - 1 < NKTILES) cp_async_wait<STAGES - 2>();
        else                           cp_async_wait<0>();
        __syncthreads();             // tile kt resident; prior-buffer readers done

        const int buf = kt % STAGES;
        const uint32_t abase = a_s32 + (uint32_t)buf * A_TILE;
        const uint32_t bbase = b_s32 + (uint32_t)buf * B_TILE;

        // One k16 step at warp-rotated order. Accumulation order differs per
        // warp but the fp32 sums are exact integers -> bit-identical result.
        auto do_step = [&](int si) {
            const int s = (si + srot) & 3;
            uint32_t a[4][4], b[2][4];
#pragma unroll
            for (int mi = 0; mi < 4; mi++) {
                int row = wm + mi * 16 + rlo;
                ldmatrix_x4(a[mi], abase + swz(row, s * 2 + chi));
            }
#pragma unroll
            for (int nq = 0; nq < 2; nq++) {
                int row = wn + nq * 16 + rlo;
                ldmatrix_x4(b[nq], bbase + swz(row, s * 2 + chi));
            }
#pragma unroll
            for (int mi = 0; mi < 4; mi++) {
#pragma unroll
                for (int nj = 0; nj < 4; nj++) {
                    uint32_t b0 = b[nj >> 1][nj & 1];      // k 0-7,  n8-tile nj
                    uint32_t b1 = b[nj >> 1][2 + (nj & 1)];// k 8-15, n8-tile nj
                    mma_bf16(acc[mi][nj], a[mi], b0, b1);
                }
            }
        };

        do_step(0);
        // Issue next-tile loads AFTER the first step: LSU burst overlaps MMA.
        if (kt + STAGES - 1 < NKTILES)
            load_tile((kt + STAGES - 1) % STAGES, kt + STAGES - 1);
        do_step(1);
        do_step(2);
        do_step(3);
    }

    // --- epilogue: acc is the EXACT integer sum as fp32; requant == reference
    const float sxw = scale_x[0] * scale_w[0];
    const int g  = lane >> 2;         // C-frag row within m8
    const int cl = (lane & 3) * 2;    // C-frag column pair

#pragma unroll
    for (int mi = 0; mi < 4; mi++) {
        int r0 = bm + wm + mi * 16 + g;
        int r1 = r0 + 8;
        float f0 = sxw / __ldg(scale_y + r0);
        float f1 = sxw / __ldg(scale_y + r1);
#pragma unroll
        for (int nj = 0; nj < 4; nj++) {
            int col = bn + wn + nj * 8 + cl;
            float q00 = quantize_f(acc[mi][nj][0], f0);
            float q01 = quantize_f(acc[mi][nj][1], f0);
            float q10 = quantize_f(acc[mi][nj][2], f1);
            float q11 = quantize_f(acc[mi][nj][3], f1);
            if (out_float) {
                float* out = (float*)out_raw;
                *reinterpret_cast<float2*>(out + (size_t)r0 * O_DIM + col) =
                    make_float2(q00, q01);
                *reinterpret_cast<float2*>(out + (size_t)r1 * O_DIM + col) =
                    make_float2(q10, q11);
            } else {
                int8_t* out = (int8_t*)out_raw;
                char2 v0, v1;
                v0.x = (int8_t)(int)q00; v0.y = (int8_t)(int)q01;
                v1.x = (int8_t)(int)q10; v1.y = (int8_t)(int)q11;
                *reinterpret_cast<char2*>(out + (size_t)r0 * O_DIM + col) = v0;
                *reinterpret_cast<char2*>(out + (size_t)r1 * O_DIM + col) = v1;
            }
        }
    }

    // Fused scale_y tail (one CTA), float mode only.
    if (out_float && blockIdx.x == 0 && blockIdx.y == 0) {
        float* tail = (float*)out_raw + (size_t)S_DIM * O_DIM;
        for (int i = tid; i < S_DIM; i += NTHREADS) tail[i] = scale_y[i];
    }
}

extern "C" void kernel_launch(void* const* d_in, const int* in_sizes, int n_in,
                              void* d_out, int out_size) {
    // Identify inputs BY ELEMENT COUNT (robust to d_in ordering).
    const void*  x_raw = nullptr;
    const void*  w_raw = nullptr;
    const float* sx = nullptr;
    const float* sw = nullptr;
    const float* sy = nullptr;
    for (int i = 0; i < n_in; i++) {
        long long n = in_sizes[i];
        if      (n == (long long)S_DIM * K_DIM) x_raw = d_in[i];
        else if (n == (long long)O_DIM * K_DIM) w_raw = d_in[i];
        else if (n == S_DIM)                    sy = (const float*)d_in[i];
        else if (n == 1) { if (!sx) sx = (const float*)d_in[i];
                           else     sw = (const float*)d_in[i]; }
    }
    if (!x_raw) x_raw = d_in[0];
    if (!w_raw) w_raw = d_in[1];
    if (!sx) sx = (const float*)d_in[2];
    if (!sw) sw = (const float*)d_in[3];
    if (!sy) sy = (const float*)d_in[4];

    const int n4x = (S_DIM * K_DIM) / 4;
    const int n4w = (O_DIM * K_DIM) / 4;
    convert_both_kernel<<<(n4x + n4w + 255) / 256, 256>>>(
        (const uint32_t*)x_raw, n4x, (const uint32_t*)w_raw, n4w);

    const long long SO = (long long)S_DIM * O_DIM;
    const int out_float = ((long long)out_size >= SO + S_DIM) ? 1 : 0;

    cudaFuncSetAttribute(bf16_gemm_requant_kernel,
                         cudaFuncAttributeMaxDynamicSharedMemorySize, SMEM_BYTES);

    dim3 grid(O_DIM / BN, S_DIM / BM);   // 32 x 64 = 2048 CTAs
    bf16_gemm_requant_kernel<<<grid, NTHREADS, SMEM_BYTES>>>(
        sx, sw, sy, d_out, out_float);
}

// round 16
// speedup vs baseline: 2.6142x; 1.0503x over previous
#include <cuda_runtime.h>
#include <cuda_bf16.h>
#include <cstdint>

// ----------------------------------------------------------------------------
// int8 GEMM (S,K)x(O,K)^T -> requantized (S,O), fused per-row scale.
// R13/R15: bf16 HMMA at 207us, tensor=59%, L1=55% -> warps are TIME-locked by
// the per-tile __syncthreads (R15 address-rotation was a null: it changed
// data, not timing). R16: mbarrier producer/consumer ring, no CTA barrier in
// the mainloop -> warps drift up to 2 tiles apart and de-phase for real.
// Math identical (fp32 accumulation of integer-valued products is EXACT:
// |sum| <= 1024*127^2 < 2^24) -> bit-identical output.
// Contract (proven): inputs promoted (int32-or-f32) -> bf16 scratch pre-pass;
// d_out = float32 [S*O out_q | S scale_y].
// ----------------------------------------------------------------------------

namespace {

constexpr int S_DIM = 8192;
constexpr int K_DIM = 1024;
constexpr int O_DIM = 4096;

constexpr int BM = 128;        // CTA tile M
constexpr int BN = 128;        // CTA tile N
constexpr int BKE = 64;        // K elements per tile (= 128 bytes per smem row)
constexpr int BKB = 128;       // K bytes per smem row (SW128 atom)
constexpr int NTHREADS = 256;  // 8 warps: 2 (M) x 4 (N), warp tile 64x32
constexpr int NKTILES = K_DIM / BKE;  // 16
constexpr int STAGES = 3;

constexpr int A_TILE = BM * BKB;     // 16 KB
constexpr int B_TILE = BN * BKB;     // 16 KB

constexpr int SMEM_BARS = 0;                   // 3 x (full,empty) pairs, 16B each
constexpr int SMEM_A    = 1024;                // 1KB alignment for swizzle
constexpr int SMEM_B    = SMEM_A + STAGES * A_TILE;
constexpr int SMEM_BYTES = SMEM_B + STAGES * B_TILE;   // 1KB + 96KB

// SW128 swizzle: 128-byte rows, 16-byte quads, quad ^= (row & 7).
__device__ __forceinline__ uint32_t swz(uint32_t row, uint32_t q) {
    return row * (uint32_t)BKB + ((q ^ (row & 7u)) << 4);
}

__device__ __forceinline__ void cp_async16(uint32_t saddr, const void* gptr) {
    asm volatile("cp.async.cg.shared.global [%0], [%1], 16;\n" :: "r"(saddr), "l"(gptr));
}

__device__ __forceinline__ void mbar_init(uint32_t mbar, uint32_t cnt) {
    asm volatile("mbarrier.init.shared.b64 [%0], %1;" :: "r"(mbar), "r"(cnt) : "memory");
}
__device__ __forceinline__ void mbar_arrive(uint32_t mbar) {
    asm volatile("mbarrier.arrive.shared.b64 _, [%0];" :: "r"(mbar) : "memory");
}
// Post one arrival on mbar when all prior cp.async of this thread complete.
__device__ __forceinline__ void cp_async_arrive(uint32_t mbar) {
    asm volatile("cp.async.mbarrier.arrive.noinc.shared::cta.b64 [%0];"
                 :: "r"(mbar) : "memory");
}
__device__ __forceinline__ void mbar_wait(uint32_t mbar, uint32_t parity) {
    uint32_t done;
    asm volatile(
        "{\n\t.reg .pred p;\n\t"
        "mbarrier.try_wait.parity.acquire.cta.shared::cta.b64 p, [%1], %2;\n\t"
        "selp.b32 %0, 1, 0, p;\n\t}" : "=r"(done) : "r"(mbar), "r"(parity) : "memory");
    if (!done) {
        asm volatile(
            "{\n\t.reg .pred P1;\n\t"
            "W_%=:\n\t"
            "mbarrier.try_wait.parity.acquire.cta.shared::cta.b64 P1, [%0], %1, 0x989680;\n\t"
            "@P1 bra.uni D_%=;\n\t"
            "bra.uni W_%=;\n\t"
            "D_%=:\n\t}" :: "r"(mbar), "r"(parity) : "memory");
    }
}

__device__ __forceinline__ void ldmatrix_x4(uint32_t r[4], uint32_t saddr) {
    asm volatile("ldmatrix.sync.aligned.m8n8.x4.shared.b16 {%0,%1,%2,%3}, [%4];\n"
                 : "=r"(r[0]), "=r"(r[1]), "=r"(r[2]), "=r"(r[3])
                 : "r"(saddr));
}

// bf16 MMA, fp32 accumulate: D(16x8) += A(16x16) * B(16x8)
__device__ __forceinline__ void mma_bf16(float c[4], const uint32_t a[4],
                                         uint32_t b0, uint32_t b1) {
    asm volatile(
        "mma.sync.aligned.m16n8k16.row.col.f32.bf16.bf16.f32 "
        "{%0,%1,%2,%3}, {%4,%5,%6,%7}, {%8,%9}, {%0,%1,%2,%3};\n"
        : "+f"(c[0]), "+f"(c[1]), "+f"(c[2]), "+f"(c[3])
        : "r"(a[0]), "r"(a[1]), "r"(a[2]), "r"(a[3]), "r"(b0), "r"(b1));
}

__device__ __forceinline__ float quantize_f(float acc, float f) {
    float v = rintf(acc * f);                 // fp32 mul + round-half-even == jnp
    return fminf(fmaxf(v, -128.0f), 127.0f);
}

// Dtype-agnostic promoted word -> small int value (proven in R8).
__device__ __forceinline__ int word_to_int(uint32_t u) {
    uint32_t hi = u >> 8;
    int v;
    if (hi == 0u || hi == 0x00FFFFFFu) v = (int)u;
    else                               v = (int)__uint_as_float(u);
    return max(-128, min(127, v));
}

} // namespace

// bf16 scratch: 16 MB + 8 MB (static device globals: allowed).
__device__ __nv_bfloat16 g_xh[(size_t)S_DIM * K_DIM];
__device__ __nv_bfloat16 g_wh[(size_t)O_DIM * K_DIM];

// Convert BOTH promoted inputs to bf16 scratch (exact for int8 range).
__global__ void convert_both_kernel(const uint32_t* __restrict__ xsrc, int n4x,
                                    const uint32_t* __restrict__ wsrc, int n4w) {
    int i = blockIdx.x * blockDim.x + threadIdx.x;
    if (i < n4x) {
        uint4 u = reinterpret_cast<const uint4*>(xsrc)[i];
        __nv_bfloat162 p0 = __floats2bfloat162_rn((float)word_to_int(u.x),
                                                  (float)word_to_int(u.y));
        __nv_bfloat162 p1 = __floats2bfloat162_rn((float)word_to_int(u.z),
                                                  (float)word_to_int(u.w));
        reinterpret_cast<__nv_bfloat162*>(g_xh)[i * 2 + 0] = p0;
        reinterpret_cast<__nv_bfloat162*>(g_xh)[i * 2 + 1] = p1;
    } else if (i < n4x + n4w) {
        int j = i - n4x;
        uint4 u = reinterpret_cast<const uint4*>(wsrc)[j];
        __nv_bfloat162 p0 = __floats2bfloat162_rn((float)word_to_int(u.x),
                                                  (float)word_to_int(u.y));
        __nv_bfloat162 p1 = __floats2bfloat162_rn((float)word_to_int(u.z),
                                                  (float)word_to_int(u.w));
        reinterpret_cast<__nv_bfloat162*>(g_wh)[j * 2 + 0] = p0;
        reinterpret_cast<__nv_bfloat162*>(g_wh)[j * 2 + 1] = p1;
    }
}

__global__ void __launch_bounds__(NTHREADS, 2)
bf16_gemm_requant_kernel(const float* __restrict__ scale_x,
                         const float* __restrict__ scale_w,
                         const float* __restrict__ scale_y,
                         void* __restrict__ out_raw,
                         int out_float) {
    extern __shared__ int8_t smem[];
    const uint32_t sbase = (uint32_t)__cvta_generic_to_shared(smem);
    const uint32_t a_s32 = sbase + SMEM_A;
    const uint32_t b_s32 = sbase + SMEM_B;
    // Barriers: full[s] = sbase + s*16, empty[s] = sbase + s*16 + 8
    auto full_bar  = [&](int s) { return sbase + SMEM_BARS + s * 16; };
    auto empty_bar = [&](int s) { return sbase + SMEM_BARS + s * 16 + 8; };

    const int tid  = threadIdx.x;
    const int lane = tid & 31;
    const int wid  = tid >> 5;
    const int wm   = (wid & 1) * 64;   // warp M offset (2 warps over 128)
    const int wn   = (wid >> 1) * 32;  // warp N offset (4 warps over 128)

    const int bm = blockIdx.y * BM;
    const int bn = blockIdx.x * BN;

    if (tid == 0) {
        for (int s = 0; s < STAGES; s++) {
            mbar_init(full_bar(s),  NTHREADS);   // one cp-completion arrival/thread
            mbar_init(empty_bar(s), NTHREADS);   // one consume arrival/thread
        }
    }
    __syncthreads();   // barriers visible before any arrive

    const __nv_bfloat16* Ag0 = g_xh + (size_t)bm * K_DIM;
    const __nv_bfloat16* Bg0 = g_wh + (size_t)bn * K_DIM;

    // Produce tile kt into stage: 8x cp.async/thread, then full arrival on copy
    // completion.
    auto produce = [&](int kt, int stage) {
        const __nv_bfloat16* Ag = Ag0 + kt * BKE;
        const __nv_bfloat16* Bg = Bg0 + kt * BKE;
        const uint32_t abase = a_s32 + (uint32_t)stage * A_TILE;
        const uint32_t bbase = b_s32 + (uint32_t)stage * B_TILE;
#pragma unroll
        for (int i = 0; i < 4; i++) {
            int idx = tid + i * NTHREADS;        // 0..1023
            int row = idx >> 3;                  // 0..127
            int q   = idx & 7;                   // 16B quad = 8 bf16
            cp_async16(abase + swz(row, q), Ag + (size_t)row * K_DIM + q * 8);
        }
#pragma unroll
        for (int i = 0; i < 4; i++) {
            int idx = tid + i * NTHREADS;
            int row = idx >> 3;
            int q   = idx & 7;
            cp_async16(bbase + swz(row, q), Bg + (size_t)row * K_DIM + q * 8);
        }
        cp_async_arrive(full_bar(stage));
    };

    float acc[4][4][4];
#pragma unroll
    for (int mi = 0; mi < 4; mi++)
#pragma unroll
        for (int nj = 0; nj < 4; nj++)
#pragma unroll
            for (int r = 0; r < 4; r++) acc[mi][nj][r] = 0.0f;

    // Prologue: produce tiles 0, 1 (fresh buffers, no empty wait needed).
    produce(0, 0);
    produce(1, 1);

    const int rlo = lane & 15;   // ldmatrix row within 16-row group
    const int chi = lane >> 4;   // k8-half select within k16 (16B quad)

    // Cursors. Consumer: tile kt -> stage kt%3, phase flips each wrap.
    // Producer: next tile = 2 -> stage 2, phase starts at 1 so waits on fresh
    // (phase-0) barriers pass immediately.
    int cons_stage = 0, cons_phase = 0;
    int prod_stage = 2, prod_phase = 1;

    for (int kt = 0; kt < NKTILES; ++kt) {
        mbar_wait(full_bar(cons_stage), cons_phase);   // tile kt resident+visible

        const uint32_t abase = a_s32 + (uint32_t)cons_stage * A_TILE;
        const uint32_t bbase = b_s32 + (uint32_t)cons_stage * B_TILE;

#pragma unroll
        for (int s = 0; s < 4; s++) {          // 4 x k16 steps within BKE=64
            uint32_t a[4][4], b[2][4];
#pragma unroll
            for (int mi = 0; mi < 4; mi++) {
                int row = wm + mi * 16 + rlo;
                ldmatrix_x4(a[mi], abase + swz(row, s * 2 + chi));
            }
#pragma unroll
            for (int nq = 0; nq < 2; nq++) {
                int row = wn + nq * 16 + rlo;
                ldmatrix_x4(b[nq], bbase + swz(row, s * 2 + chi));
            }
#pragma unroll
            for (int mi = 0; mi < 4; mi++) {
#pragma unroll
                for (int nj = 0; nj < 4; nj++) {
                    uint32_t b0 = b[nj >> 1][nj & 1];      // k 0-7,  n8-tile nj
                    uint32_t b1 = b[nj >> 1][2 + (nj & 1)];// k 8-15, n8-tile nj
                    mma_bf16(acc[mi][nj], a[mi], b0, b1);
                }
            }
        }

        mbar_arrive(empty_bar(cons_stage));            // done reading this stage
        if (++cons_stage == STAGES) { cons_stage = 0; cons_phase ^= 1; }

        if (kt + 2 < NKTILES) {
            mbar_wait(empty_bar(prod_stage), prod_phase);  // buffer free?
            produce(kt + 2, prod_stage);
            if (++prod_stage == STAGES) { prod_stage = 0; prod_phase ^= 1; }
        }
    }

    // --- epilogue: acc is the EXACT integer sum as fp32; requant == reference
    const float sxw = scale_x[0] * scale_w[0];
    const int g  = lane >> 2;         // C-frag row within m8
    const int cl = (lane & 3) * 2;    // C-frag column pair

#pragma unroll
    for (int mi = 0; mi < 4; mi++) {
        int r0 = bm + wm + mi * 16 + g;
        int r1 = r0 + 8;
        float f0 = sxw / __ldg(scale_y + r0);
        float f1 = sxw / __ldg(scale_y + r1);
#pragma unroll
        for (int nj = 0; nj < 4; nj++) {
            int col = bn + wn + nj * 8 + cl;
            float q00 = quantize_f(acc[mi][nj][0], f0);
            float q01 = quantize_f(acc[mi][nj][1], f0);
            float q10 = quantize_f(acc[mi][nj][2], f1);
            float q11 = quantize_f(acc[mi][nj][3], f1);
            if (out_float) {
                float* out = (float*)out_raw;
                *reinterpret_cast<float2*>(out + (size_t)r0 * O_DIM + col) =
                    make_float2(q00, q01);
                *reinterpret_cast<float2*>(out + (size_t)r1 * O_DIM + col) =
                    make_float2(q10, q11);
            } else {
                int8_t* out = (int8_t*)out_raw;
                char2 v0, v1;
                v0.x = (int8_t)(int)q00; v0.y = (int8_t)(int)q01;
                v1.x = (int8_t)(int)q10; v1.y = (int8_t)(int)q11;
                *reinterpret_cast<char2*>(out + (size_t)r0 * O_DIM + col) = v0;
                *reinterpret_cast<char2*>(out + (size_t)r1 * O_DIM + col) = v1;
            }
        }
    }

    // Fused scale_y tail (one CTA), float mode only.
    if (out_float && blockIdx.x == 0 && blockIdx.y == 0) {
        float* tail = (float*)out_raw + (size_t)S_DIM * O_DIM;
        for (int i = tid; i < S_DIM; i += NTHREADS) tail[i] = scale_y[i];
    }
}

extern "C" void kernel_launch(void* const* d_in, const int* in_sizes, int n_in,
                              void* d_out, int out_size) {
    // Identify inputs BY ELEMENT COUNT (robust to d_in ordering).
    const void*  x_raw = nullptr;
    const void*  w_raw = nullptr;
    const float* sx = nullptr;
    const float* sw = nullptr;
    const float* sy = nullptr;
    for (int i = 0; i < n_in; i++) {
        long long n = in_sizes[i];
        if      (n == (long long)S_DIM * K_DIM) x_raw = d_in[i];
        else if (n == (long long)O_DIM * K_DIM) w_raw = d_in[i];
        else if (n == S_DIM)                    sy = (const float*)d_in[i];
        else if (n == 1) { if (!sx) sx = (const float*)d_in[i];
                           else     sw = (const float*)d_in[i]; }
    }
    if (!x_raw) x_raw = d_in[0];
    if (!w_raw) w_raw = d_in[1];
    if (!sx) sx = (const float*)d_in[2];
    if (!sw) sw = (const float*)d_in[3];
    if (!sy) sy = (const float*)d_in[4];

    const int n4x = (S_DIM * K_DIM) / 4;
    const int n4w = (O_DIM * K_DIM) / 4;
    convert_both_kernel<<<(n4x + n4w + 255) / 256, 256>>>(
        (const uint32_t*)x_raw, n4x, (const uint32_t*)w_raw, n4w);

    const long long SO = (long long)S_DIM * O_DIM;
    const int out_float = ((long long)out_size >= SO + S_DIM) ? 1 : 0;

    cudaFuncSetAttribute(bf16_gemm_requant_kernel,
                         cudaFuncAttributeMaxDynamicSharedMemorySize, SMEM_BYTES);

    dim3 grid(O_DIM / BN, S_DIM / BM);   // 32 x 64 = 2048 CTAs
    bf16_gemm_requant_kernel<<<grid, NTHREADS, SMEM_BYTES>>>(
        sx, sw, sy, d_out, out_float);
}

// round 17
// speedup vs baseline: 2.6188x; 1.0018x over previous
#include <cuda_runtime.h>
#include <cuda_bf16.h>
#include <cstdint>

// ----------------------------------------------------------------------------
// int8 GEMM (S,K)x(O,K)^T -> requantized (S,O), fused per-row scale.
// R16: mbarrier ring -> 197.1us (GEMM 181.3), tensor=62.4%, fma=19.4%.
// fma pipe load is IMAD addressing: swz() recomputed per ldmatrix. Since
// row&7 == rlo&7 for ALL fragment rows (wm/mi*16/wn/nq*16 are multiples of
// 8), the swizzle offset is a per-warp 4-entry table: off[s]=((2s+chi)^r7)<<4.
// R17: hoist all addressing (1 IADD per ldsm), B-frags issued first, MMAs
// start on earliest-loaded fragments. Math untouched -> bit-identical.
// Contract (proven): inputs promoted (int32-or-f32) -> bf16 scratch pre-pass;
// d_out = float32 [S*O out_q | S scale_y].
// ----------------------------------------------------------------------------

namespace {

constexpr int S_DIM = 8192;
constexpr int K_DIM = 1024;
constexpr int O_DIM = 4096;

constexpr int BM = 128;        // CTA tile M
constexpr int BN = 128;        // CTA tile N
constexpr int BKE = 64;        // K elements per tile (= 128 bytes per smem row)
constexpr int BKB = 128;       // K bytes per smem row (SW128 atom)
constexpr int NTHREADS = 256;  // 8 warps: 2 (M) x 4 (N), warp tile 64x32
constexpr int NKTILES = K_DIM / BKE;  // 16
constexpr int STAGES = 3;

constexpr int A_TILE = BM * BKB;     // 16 KB
constexpr int B_TILE = BN * BKB;     // 16 KB

constexpr int SMEM_BARS = 0;                   // 3 x (full,empty) pairs, 16B each
constexpr int SMEM_A    = 1024;                // 1KB alignment for swizzle
constexpr int SMEM_B    = SMEM_A + STAGES * A_TILE;
constexpr int SMEM_BYTES = SMEM_B + STAGES * B_TILE;   // 1KB + 96KB

// SW128 swizzle: 128-byte rows, 16-byte quads, quad ^= (row & 7).
__device__ __forceinline__ uint32_t swz(uint32_t row, uint32_t q) {
    return row * (uint32_t)BKB + ((q ^ (row & 7u)) << 4);
}

__device__ __forceinline__ void cp_async16(uint32_t saddr, const void* gptr) {
    asm volatile("cp.async.cg.shared.global [%0], [%1], 16;\n" :: "r"(saddr), "l"(gptr));
}

__device__ __forceinline__ void mbar_init(uint32_t mbar, uint32_t cnt) {
    asm volatile("mbarrier.init.shared.b64 [%0], %1;" :: "r"(mbar), "r"(cnt) : "memory");
}
__device__ __forceinline__ void mbar_arrive(uint32_t mbar) {
    asm volatile("mbarrier.arrive.shared.b64 _, [%0];" :: "r"(mbar) : "memory");
}
// Post one arrival on mbar when all prior cp.async of this thread complete.
__device__ __forceinline__ void cp_async_arrive(uint32_t mbar) {
    asm volatile("cp.async.mbarrier.arrive.noinc.shared::cta.b64 [%0];"
                 :: "r"(mbar) : "memory");
}
__device__ __forceinline__ void mbar_wait(uint32_t mbar, uint32_t parity) {
    uint32_t done;
    asm volatile(
        "{\n\t.reg .pred p;\n\t"
        "mbarrier.try_wait.parity.acquire.cta.shared::cta.b64 p, [%1], %2;\n\t"
        "selp.b32 %0, 1, 0, p;\n\t}" : "=r"(done) : "r"(mbar), "r"(parity) : "memory");
    if (!done) {
        asm volatile(
            "{\n\t.reg .pred P1;\n\t"
            "W_%=:\n\t"
            "mbarrier.try_wait.parity.acquire.cta.shared::cta.b64 P1, [%0], %1, 0x989680;\n\t"
            "@P1 bra.uni D_%=;\n\t"
            "bra.uni W_%=;\n\t"
            "D_%=:\n\t}" :: "r"(mbar), "r"(parity) : "memory");
    }
}

__device__ __forceinline__ void ldmatrix_x4(uint32_t r[4], uint32_t saddr) {
    asm volatile("ldmatrix.sync.aligned.m8n8.x4.shared.b16 {%0,%1,%2,%3}, [%4];\n"
                 : "=r"(r[0]), "=r"(r[1]), "=r"(r[2]), "=r"(r[3])
                 : "r"(saddr));
}

// bf16 MMA, fp32 accumulate: D(16x8) += A(16x16) * B(16x8)
__device__ __forceinline__ void mma_bf16(float c[4], const uint32_t a[4],
                                         uint32_t b0, uint32_t b1) {
    asm volatile(
        "mma.sync.aligned.m16n8k16.row.col.f32.bf16.bf16.f32 "
        "{%0,%1,%2,%3}, {%4,%5,%6,%7}, {%8,%9}, {%0,%1,%2,%3};\n"
        : "+f"(c[0]), "+f"(c[1]), "+f"(c[2]), "+f"(c[3])
        : "r"(a[0]), "r"(a[1]), "r"(a[2]), "r"(a[3]), "r"(b0), "r"(b1));
}

__device__ __forceinline__ float quantize_f(float acc, float f) {
    float v = rintf(acc * f);                 // fp32 mul + round-half-even == jnp
    return fminf(fmaxf(v, -128.0f), 127.0f);
}

// Dtype-agnostic promoted word -> small int value (proven in R8).
__device__ __forceinline__ int word_to_int(uint32_t u) {
    uint32_t hi = u >> 8;
    int v;
    if (hi == 0u || hi == 0x00FFFFFFu) v = (int)u;
    else                               v = (int)__uint_as_float(u);
    return max(-128, min(127, v));
}

} // namespace

// bf16 scratch: 16 MB + 8 MB (static device globals: allowed).
__device__ __nv_bfloat16 g_xh[(size_t)S_DIM * K_DIM];
__device__ __nv_bfloat16 g_wh[(size_t)O_DIM * K_DIM];

// Convert BOTH promoted inputs to bf16 scratch (exact for int8 range).
__global__ void convert_both_kernel(const uint32_t* __restrict__ xsrc, int n4x,
                                    const uint32_t* __restrict__ wsrc, int n4w) {
    int i = blockIdx.x * blockDim.x + threadIdx.x;
    if (i < n4x) {
        uint4 u = reinterpret_cast<const uint4*>(xsrc)[i];
        __nv_bfloat162 p0 = __floats2bfloat162_rn((float)word_to_int(u.x),
                                                  (float)word_to_int(u.y));
        __nv_bfloat162 p1 = __floats2bfloat162_rn((float)word_to_int(u.z),
                                                  (float)word_to_int(u.w));
        reinterpret_cast<__nv_bfloat162*>(g_xh)[i * 2 + 0] = p0;
        reinterpret_cast<__nv_bfloat162*>(g_xh)[i * 2 + 1] = p1;
    } else if (i < n4x + n4w) {
        int j = i - n4x;
        uint4 u = reinterpret_cast<const uint4*>(wsrc)[j];
        __nv_bfloat162 p0 = __floats2bfloat162_rn((float)word_to_int(u.x),
                                                  (float)word_to_int(u.y));
        __nv_bfloat162 p1 = __floats2bfloat162_rn((float)word_to_int(u.z),
                                                  (float)word_to_int(u.w));
        reinterpret_cast<__nv_bfloat162*>(g_wh)[j * 2 + 0] = p0;
        reinterpret_cast<__nv_bfloat162*>(g_wh)[j * 2 + 1] = p1;
    }
}

__global__ void __launch_bounds__(NTHREADS, 2)
bf16_gemm_requant_kernel(const float* __restrict__ scale_x,
                         const float* __restrict__ scale_w,
                         const float* __restrict__ scale_y,
                         void* __restrict__ out_raw,
                         int out_float) {
    extern __shared__ int8_t smem[];
    const uint32_t sbase = (uint32_t)__cvta_generic_to_shared(smem);
    const uint32_t a_s32 = sbase + SMEM_A;
    const uint32_t b_s32 = sbase + SMEM_B;
    auto full_bar  = [&](int s) { return sbase + SMEM_BARS + s * 16; };
    auto empty_bar = [&](int s) { return sbase + SMEM_BARS + s * 16 + 8; };

    const int tid  = threadIdx.x;
    const int lane = tid & 31;
    const int wid  = tid >> 5;
    const int wm   = (wid & 1) * 64;   // warp M offset (2 warps over 128)
    const int wn   = (wid >> 1) * 32;  // warp N offset (4 warps over 128)

    const int bm = blockIdx.y * BM;
    const int bn = blockIdx.x * BN;

    if (tid == 0) {
        for (int s = 0; s < STAGES; s++) {
            mbar_init(full_bar(s),  NTHREADS);
            mbar_init(empty_bar(s), NTHREADS);
        }
    }
    __syncthreads();   // barriers visible before any arrive

    const __nv_bfloat16* Ag0 = g_xh + (size_t)bm * K_DIM;
    const __nv_bfloat16* Bg0 = g_wh + (size_t)bn * K_DIM;

    auto produce = [&](int kt, int stage) {
        const __nv_bfloat16* Ag = Ag0 + kt * BKE;
        const __nv_bfloat16* Bg = Bg0 + kt * BKE;
        const uint32_t abase = a_s32 + (uint32_t)stage * A_TILE;
        const uint32_t bbase = b_s32 + (uint32_t)stage * B_TILE;
#pragma unroll
        for (int i = 0; i < 4; i++) {
            int idx = tid + i * NTHREADS;        // 0..1023
            int row = idx >> 3;                  // 0..127
            int q   = idx & 7;                   // 16B quad = 8 bf16
            cp_async16(abase + swz(row, q), Ag + (size_t)row * K_DIM + q * 8);
        }
#pragma unroll
        for (int i = 0; i < 4; i++) {
            int idx = tid + i * NTHREADS;
            int row = idx >> 3;
            int q   = idx & 7;
            cp_async16(bbase + swz(row, q), Bg + (size_t)row * K_DIM + q * 8);
        }
        cp_async_arrive(full_bar(stage));
    };

    float acc[4][4][4];
#pragma unroll
    for (int mi = 0; mi < 4; mi++)
#pragma unroll
        for (int nj = 0; nj < 4; nj++)
#pragma unroll
            for (int r = 0; r < 4; r++) acc[mi][nj][r] = 0.0f;

    // Prologue: produce tiles 0, 1 (fresh buffers, no empty wait needed).
    produce(0, 0);
    produce(1, 1);

    // ---- hoisted fragment addressing ----
    // All fragment rows of this warp share row&7 == rlo&7, so the swizzled
    // quad offset is a per-warp 4-entry table indexed by k16-step only.
    const int rlo = lane & 15;            // ldmatrix row within 16-row group
    const int chi = lane >> 4;            // k8-half select within k16
    const uint32_t r7 = (uint32_t)(rlo & 7);
    uint32_t off[4];
#pragma unroll
    for (int s = 0; s < 4; s++)
        off[s] = ((((uint32_t)(s * 2 + chi)) ^ r7) << 4);
    uint32_t arow[4], brow[2];
#pragma unroll
    for (int mi = 0; mi < 4; mi++) arow[mi] = (uint32_t)(wm + mi * 16 + rlo) * BKB;
#pragma unroll
    for (int nq = 0; nq < 2; nq++) brow[nq] = (uint32_t)(wn + nq * 16 + rlo) * BKB;

    int cons_stage = 0, cons_phase = 0;
    int prod_stage = 2, prod_phase = 1;

    for (int kt = 0; kt < NKTILES; ++kt) {
        mbar_wait(full_bar(cons_stage), cons_phase);   // tile kt resident+visible

        const uint32_t abase = a_s32 + (uint32_t)cons_stage * A_TILE;
        const uint32_t bbase = b_s32 + (uint32_t)cons_stage * B_TILE;
        uint32_t ab0 = abase + arow[0], ab1 = abase + arow[1];
        uint32_t ab2 = abase + arow[2], ab3 = abase + arow[3];
        uint32_t bb0 = bbase + brow[0], bb1 = bbase + brow[1];

#pragma unroll
        for (int s = 0; s < 4; s++) {          // 4 x k16 steps within BKE=64
            const uint32_t o = off[s];
            uint32_t a[4][4], b[2][4];
            // B first, then A: the first MMA (a[0], b[0]) consumes the
            // earliest-issued loads -> minimal exposed LDSM latency.
            ldmatrix_x4(b[0], bb0 + o);
            ldmatrix_x4(b[1], bb1 + o);
            ldmatrix_x4(a[0], ab0 + o);
            ldmatrix_x4(a[1], ab1 + o);
            ldmatrix_x4(a[2], ab2 + o);
            ldmatrix_x4(a[3], ab3 + o);
#pragma unroll
            for (int mi = 0; mi < 4; mi++) {
#pragma unroll
                for (int nj = 0; nj < 4; nj++) {
                    uint32_t b0 = b[nj >> 1][nj & 1];      // k 0-7,  n8-tile nj
                    uint32_t b1 = b[nj >> 1][2 + (nj & 1)];// k 8-15, n8-tile nj
                    mma_bf16(acc[mi][nj], a[mi], b0, b1);
                }
            }
        }

        mbar_arrive(empty_bar(cons_stage));            // done reading this stage
        if (++cons_stage == STAGES) { cons_stage = 0; cons_phase ^= 1; }

        if (kt + 2 < NKTILES) {
            mbar_wait(empty_bar(prod_stage), prod_phase);  // buffer free?
            produce(kt + 2, prod_stage);
            if (++prod_stage == STAGES) { prod_stage = 0; prod_phase ^= 1; }
        }
    }

    // --- epilogue: acc is the EXACT integer sum as fp32; requant == reference
    const float sxw = scale_x[0] * scale_w[0];
    const int g  = lane >> 2;         // C-frag row within m8
    const int cl = (lane & 3) * 2;    // C-frag column pair

#pragma unroll
    for (int mi = 0; mi < 4; mi++) {
        int r0 = bm + wm + mi * 16 + g;
        int r1 = r0 + 8;
        float f0 = sxw / __ldg(scale_y + r0);
        float f1 = sxw / __ldg(scale_y + r1);
#pragma unroll
        for (int nj = 0; nj < 4; nj++) {
            int col = bn + wn + nj * 8 + cl;
            float q00 = quantize_f(acc[mi][nj][0], f0);
            float q01 = quantize_f(acc[mi][nj][1], f0);
            float q10 = quantize_f(acc[mi][nj][2], f1);
            float q11 = quantize_f(acc[mi][nj][3], f1);
            if (out_float) {
                float* out = (float*)out_raw;
                *reinterpret_cast<float2*>(out + (size_t)r0 * O_DIM + col) =
                    make_float2(q00, q01);
                *reinterpret_cast<float2*>(out + (size_t)r1 * O_DIM + col) =
                    make_float2(q10, q11);
            } else {
                int8_t* out = (int8_t*)out_raw;
                char2 v0, v1;
                v0.x = (int8_t)(int)q00; v0.y = (int8_t)(int)q01;
                v1.x = (int8_t)(int)q10; v1.y = (int8_t)(int)q11;
                *reinterpret_cast<char2*>(out + (size_t)r0 * O_DIM + col) = v0;
                *reinterpret_cast<char2*>(out + (size_t)r1 * O_DIM + col) = v1;
            }
        }
    }

    // Fused scale_y tail (one CTA), float mode only.
    if (out_float && blockIdx.x == 0 && blockIdx.y == 0) {
        float* tail = (float*)out_raw + (size_t)S_DIM * O_DIM;
        for (int i = tid; i < S_DIM; i += NTHREADS) tail[i] = scale_y[i];
    }
}

extern "C" void kernel_launch(void* const* d_in, const int* in_sizes, int n_in,
                              void* d_out, int out_size) {
    // Identify inputs BY ELEMENT COUNT (robust to d_in ordering).
    const void*  x_raw = nullptr;
    const void*  w_raw = nullptr;
    const float* sx = nullptr;
    const float* sw = nullptr;
    const float* sy = nullptr;
    for (int i = 0; i < n_in; i++) {
        long long n = in_sizes[i];
        if      (n == (long long)S_DIM * K_DIM) x_raw = d_in[i];
        else if (n == (long long)O_DIM * K_DIM) w_raw = d_in[i];
        else if (n == S_DIM)                    sy = (const float*)d_in[i];
        else if (n == 1) { if (!sx) sx = (const float*)d_in[i];
                           else     sw = (const float*)d_in[i]; }
    }
    if (!x_raw) x_raw = d_in[0];
    if (!w_raw) w_raw = d_in[1];
    if (!sx) sx = (const float*)d_in[2];
    if (!sw) sw = (const float*)d_in[3];
    if (!sy) sy = (const float*)d_in[4];

    const int n4x = (S_DIM * K_DIM) / 4;
    const int n4w = (O_DIM * K_DIM) / 4;
    convert_both_kernel<<<(n4x + n4w + 255) / 256, 256>>>(
        (const uint32_t*)x_raw, n4x, (const uint32_t*)w_raw, n4w);

    const long long SO = (long long)S_DIM * O_DIM;
    const int out_float = ((long long)out_size >= SO + S_DIM) ? 1 : 0;

    cudaFuncSetAttribute(bf16_gemm_requant_kernel,
                         cudaFuncAttributeMaxDynamicSharedMemorySize, SMEM_BYTES);

    dim3 grid(O_DIM / BN, S_DIM / BM);   // 32 x 64 = 2048 CTAs
    bf16_gemm_requant_kernel<<<grid, NTHREADS, SMEM_BYTES>>>(
        sx, sw, sy, d_out, out_float);
}